// round 6
// baseline (speedup 1.0000x reference)
#include <cuda_runtime.h>
#include <cuda_bf16.h>
#include <cstdint>

// Problem dims
#define BB   32
#define TT   512
#define II   512
#define HH   1024
#define OO   512
#define MM   (BB*TT)

#define RNN_BLOCKS 64

// ---------------- scratch (static device globals) ---------------------------
__device__ float g_pre[MM * HH];
__device__ float g_logits[MM * OO];
__device__ float g_zfallback[MM * HH];

__device__ __nv_bfloat16 g_xhi[MM * II],    g_xlo[MM * II];
__device__ __nv_bfloat16 g_wih_hi[HH * II], g_wih_lo[HH * II];
__device__ __nv_bfloat16 g_wout_hi[OO * HH], g_wout_lo[OO * HH];
__device__ __nv_bfloat16 g_zhi[MM * HH],    g_zlo[MM * HH];
__device__ __nv_bfloat16 g_h0hi[BB * HH],   g_h0lo[BB * HH];

// per-block spread flags (128B apart), one set per batch group
__device__ unsigned g_flags[2][RNN_BLOCKS * 32];

// ---------------- helpers ----------------------------------------------------
__device__ __forceinline__ void mma16816(float& d0, float& d1, float& d2, float& d3,
                                         uint32_t a0, uint32_t a1, uint32_t a2, uint32_t a3,
                                         uint32_t b0, uint32_t b1)
{
    asm volatile(
        "mma.sync.aligned.m16n8k16.row.col.f32.bf16.bf16.f32 "
        "{%0,%1,%2,%3},{%4,%5,%6,%7},{%8,%9},{%0,%1,%2,%3};"
        : "+f"(d0), "+f"(d1), "+f"(d2), "+f"(d3)
        : "r"(a0), "r"(a1), "r"(a2), "r"(a3), "r"(b0), "r"(b1));
}

__device__ __forceinline__ void ldsm4(uint32_t& r0, uint32_t& r1, uint32_t& r2, uint32_t& r3,
                                      uint32_t addr)
{
    asm volatile("ldmatrix.sync.aligned.m8n8.x4.shared.b16 {%0,%1,%2,%3}, [%4];"
                 : "=r"(r0), "=r"(r1), "=r"(r2), "=r"(r3) : "r"(addr));
}

__device__ __forceinline__ uint32_t lds32(uint32_t a) {
    uint32_t v;
    asm volatile("ld.shared.b32 %0, [%1];" : "=r"(v) : "r"(a));
    return v;
}

__device__ __forceinline__ void cpa16(uint32_t s, const void* g) {
    asm volatile("cp.async.cg.shared.global [%0], [%1], 16;" :: "r"(s), "l"(g));
}

__device__ __forceinline__ uint32_t pack_hi2(float x, float y) {
    __nv_bfloat162 t;
    t.x = __float2bfloat16(x);
    t.y = __float2bfloat16(y);
    return *reinterpret_cast<uint32_t*>(&t);
}
__device__ __forceinline__ uint32_t pack_lo2(float x, float y) {
    __nv_bfloat16 hx = __float2bfloat16(x), hy = __float2bfloat16(y);
    __nv_bfloat162 t;
    t.x = __float2bfloat16(x - __bfloat162float(hx));
    t.y = __float2bfloat16(y - __bfloat162float(hy));
    return *reinterpret_cast<uint32_t*>(&t);
}

__device__ __forceinline__ void flag_store(unsigned* p, unsigned v) {
    asm volatile("st.release.gpu.u32 [%0], %1;" :: "l"(p), "r"(v));
}
__device__ __forceinline__ void flag_wait(const unsigned* p, unsigned target) {
    unsigned v;
    do {
        asm volatile("ld.acquire.gpu.u32 %0, [%1];" : "=r"(v) : "l"(p));
    } while ((int)(v - target) < 0);
}

// ---------------- persistent Elman recurrence (2-group pipeline) -------------
// 64 blocks x 256 threads. Block jc owns j in [jc*16, jc*16+16).
// Batch split into 2 groups of 16 rows (independent chains). Per iter:
// compute one group's step with mma (k split 8-way over warps, W in regs);
// mid-compute, flag-wait + cp.async-stage the other group's h. One flag
// barrier (spread, atomic-free) per group-step.
#define GROW   16
#define HROW   2064                       // 1024 bf16 + 16B pad
#define BUFB   (GROW * HROW)              // 33024 B per (group,hi|lo)
#define SM_PS  (4 * BUFB)                 // psum region
#define PSROW  18                         // padded floats per psum row
#define RNN_SMEM (SM_PS + 8 * GROW * PSROW * 4)

__global__ __launch_bounds__(256, 1)
void rnn_persistent(const float* __restrict__ pre,
                    const float* __restrict__ W_hh,
                    float* __restrict__ z_out)
{
    extern __shared__ __align__(16) char dsm[];
    const uint32_t sb = (uint32_t)__cvta_generic_to_shared(dsm);

    const int tid  = threadIdx.x;
    const int wid  = tid >> 5;
    const int lane = tid & 31;
    const int grp  = lane >> 2;       // 0..7
    const int tig  = lane & 3;        // 0..3
    const int jc   = blockIdx.x;      // 0..63
    const int kw   = wid;             // k chunk of 128 per warp

    // replay-safe base (own slot, equal across blocks at launch)
    const unsigned base = g_flags[0][blockIdx.x * 32];

    // ---- prologue: stage h0 for both groups (2 commit groups) ----
    #pragma unroll
    for (int gg = 0; gg < 2; gg++) {
        #pragma unroll
        for (int r = 0; r < 8; r++) {
            int idx = tid + r * 256;          // 0..2047
            int row = idx >> 7;               // 0..15
            int c   = idx & 127;              // 16B chunk
            size_t gof = (size_t)(gg * GROW + row) * HH + c * 8;
            cpa16(sb + gg * 2 * BUFB + row * HROW + c * 16,        g_h0hi + gof);
            cpa16(sb + gg * 2 * BUFB + BUFB + row * HROW + c * 16, g_h0lo + gof);
        }
        asm volatile("cp.async.commit_group;" ::: "memory");
    }

    // ---- preload W fragments (hi/lo) into registers, whole run ----
    uint32_t whi0[2][8], whi1[2][8], wlo0[2][8], wlo1[2][8];
    #pragma unroll
    for (int nt = 0; nt < 2; nt++) {
        const int jrow = jc * 16 + nt * 8 + grp;
        const float* Wr = W_hh + (size_t)jrow * HH + kw * 128;
        #pragma unroll
        for (int ki = 0; ki < 8; ki++) {
            int k0 = ki * 16 + tig * 2;
            float w0 = Wr[k0],     w1 = Wr[k0 + 1];
            float w2 = Wr[k0 + 8], w3 = Wr[k0 + 9];
            whi0[nt][ki] = pack_hi2(w0, w1);
            wlo0[nt][ki] = pack_lo2(w0, w1);
            whi1[nt][ki] = pack_hi2(w2, w3);
            wlo1[nt][ki] = pack_lo2(w2, w3);
        }
    }

    // ldmatrix per-lane address component for A (m16k16)
    const uint32_t lrow = (lane & 7) + ((lane >> 3) & 1) * 8;   // 0..15
    const uint32_t aoff = lrow * HROW + (uint32_t)kw * 256 + ((uint32_t)lane >> 4) * 16;

    float* const psum = (float*)(dsm + SM_PS);

    // phase-B mapping (tid<128): b=tid>>3 (0..15), jpair=(tid&7)*2
    const int pbB = tid >> 3;
    const int pbJ = (tid & 7) * 2;

    for (int s = 0; s < 2 * TT; s++) {
        const int g = s & 1;
        const int t = s >> 1;
        const uint32_t bufhi = sb + (uint32_t)g * 2 * BUFB;
        const uint32_t buflo = bufhi + BUFB;

        // top: buf[g] must be resident
        asm volatile("cp.async.wait_group 0;" ::: "memory");
        __syncthreads();

        // prefetch pre for phase B
        float2 pre2 = make_float2(0.f, 0.f);
        if (tid < 128)
            pre2 = *(const float2*)&pre[((size_t)(g * GROW + pbB) * TT + t) * HH + jc * 16 + pbJ];

        // ---- terms 1+2: h_hi x (W_hi, W_lo) ----
        float a1[2][4] = {{0,0,0,0},{0,0,0,0}};
        float a2[2][4] = {{0,0,0,0},{0,0,0,0}};
        #pragma unroll
        for (int ki = 0; ki < 8; ki++) {
            uint32_t h0r, h1r, h2r, h3r;
            ldsm4(h0r, h1r, h2r, h3r, bufhi + aoff + ki * 32);
            #pragma unroll
            for (int nt = 0; nt < 2; nt++) {
                mma16816(a1[nt][0], a1[nt][1], a1[nt][2], a1[nt][3],
                         h0r, h1r, h2r, h3r, whi0[nt][ki], whi1[nt][ki]);
                mma16816(a2[nt][0], a2[nt][1], a2[nt][2], a2[nt][3],
                         h0r, h1r, h2r, h3r, wlo0[nt][ki], wlo1[nt][ki]);
            }
        }

        // ---- mid: flag-wait + stage next iter's group ----
        {
            const int s1 = s + 1;
            if (s1 < 2 * TT) {
                const int g2 = s1 & 1;
                const int t2 = s1 >> 1;
                if (t2 >= 1) {
                    if (tid < RNN_BLOCKS)
                        flag_wait(&g_flags[g2][tid * 32], base + (unsigned)t2);
                    __syncthreads();
                    const uint32_t dsthi = sb + (uint32_t)g2 * 2 * BUFB;
                    #pragma unroll
                    for (int r = 0; r < 8; r++) {
                        int idx = tid + r * 256;
                        int row = idx >> 7;
                        int c   = idx & 127;
                        size_t gof = ((size_t)(g2 * GROW + row) * TT + (t2 - 1)) * HH + c * 8;
                        cpa16(dsthi + row * HROW + c * 16,        g_zhi + gof);
                        cpa16(dsthi + BUFB + row * HROW + c * 16, g_zlo + gof);
                    }
                    asm volatile("cp.async.commit_group;" ::: "memory");
                }
            }
        }

        // ---- term 3: h_lo x W_hi ----
        float a3[2][4] = {{0,0,0,0},{0,0,0,0}};
        #pragma unroll
        for (int ki = 0; ki < 8; ki++) {
            uint32_t l0r, l1r, l2r, l3r;
            ldsm4(l0r, l1r, l2r, l3r, buflo + aoff + ki * 32);
            #pragma unroll
            for (int nt = 0; nt < 2; nt++) {
                mma16816(a3[nt][0], a3[nt][1], a3[nt][2], a3[nt][3],
                         l0r, l1r, l2r, l3r, whi0[nt][ki], whi1[nt][ki]);
            }
        }

        // ---- per-warp k-partials to SMEM ----
        #pragma unroll
        for (int nt = 0; nt < 2; nt++) {
            int jj = nt * 8 + tig * 2;
            float c0 = a1[nt][0] + a2[nt][0] + a3[nt][0];
            float c1 = a1[nt][1] + a2[nt][1] + a3[nt][1];
            float c2 = a1[nt][2] + a2[nt][2] + a3[nt][2];
            float c3 = a1[nt][3] + a2[nt][3] + a3[nt][3];
            float* p = psum + (size_t)kw * (GROW * PSROW) + grp * PSROW + jj;
            *(float2*)p                  = make_float2(c0, c1);
            *(float2*)(p + 8 * PSROW)    = make_float2(c2, c3);
        }
        __syncthreads();

        // ---- phase B: reduce 8 k-partials, tanh, publish z ----
        if (tid < 128) {
            float s0 = pre2.x, s1v = pre2.y;
            #pragma unroll
            for (int kk = 0; kk < 8; kk++) {
                float2 p = *(float2*)&psum[kk * (GROW * PSROW) + pbB * PSROW + pbJ];
                s0 += p.x; s1v += p.y;
            }
            float h0v = tanhf(s0);
            float h1v = tanhf(s1v);
            size_t zidx = ((size_t)(g * GROW + pbB) * TT + t) * HH + jc * 16 + pbJ;
            *(float2*)&z_out[zidx]   = make_float2(h0v, h1v);
            *(uint32_t*)&g_zhi[zidx] = pack_hi2(h0v, h1v);
            *(uint32_t*)&g_zlo[zidx] = pack_lo2(h0v, h1v);
        }
        __syncthreads();
        if (tid == 0)
            flag_store(&g_flags[g][blockIdx.x * 32], base + (unsigned)t + 1u);
    }
}

// ---------------- fp32 -> bf16 hi/lo split -----------------------------------
__global__ __launch_bounds__(256)
void split_bf16(const float* __restrict__ src,
                __nv_bfloat16* __restrict__ hi,
                __nv_bfloat16* __restrict__ lo, int n)
{
    int i = blockIdx.x * 256 + threadIdx.x;
    if (i < n) {
        float x = src[i];
        __nv_bfloat16 h = __float2bfloat16(x);
        hi[i] = h;
        lo[i] = __float2bfloat16(x - __bfloat162float(h));
    }
}

// ---------------- mma.sync bf16 3-split GEMM ---------------------------------
#define GT_BYTES  (128 * 80)
#define GBUF      (4 * GT_BYTES)
#define GSMEM     (2 * GBUF)

__global__ __launch_bounds__(256)
void bsgemm(int M, int N, int K,
            const __nv_bfloat16* __restrict__ Ahi, const __nv_bfloat16* __restrict__ Alo,
            const __nv_bfloat16* __restrict__ Bhi, const __nv_bfloat16* __restrict__ Blo,
            const float* __restrict__ bias1, const float* __restrict__ bias2,
            float* __restrict__ C)
{
    extern __shared__ __align__(16) char dsm[];
    const uint32_t sb = (uint32_t)__cvta_generic_to_shared(dsm);

    const int tid  = threadIdx.x;
    const int wid  = tid >> 5;
    const int lane = tid & 31;
    const int grp  = lane >> 2;
    const int tig  = lane & 3;
    const int wm   = wid & 1;
    const int wn   = wid >> 1;
    const int m0   = blockIdx.x * 128;
    const int n0   = blockIdx.y * 128;

    float acc[4][4][4];
    #pragma unroll
    for (int i = 0; i < 4; i++)
        #pragma unroll
        for (int j = 0; j < 4; j++)
            #pragma unroll
            for (int q = 0; q < 4; q++) acc[i][j][q] = 0.f;

    const int lrow = tid >> 2;
    const int lc16 = tid & 3;

    auto issue = [&](int kt, int buf) {
        #pragma unroll
        for (int r = 0; r < 2; r++) {
            int row = lrow + r * 64;
            uint32_t so = (uint32_t)buf * GBUF + row * 80 + lc16 * 16;
            size_t goA = (size_t)(m0 + row) * K + kt * 32 + lc16 * 8;
            size_t goB = (size_t)(n0 + row) * K + kt * 32 + lc16 * 8;
            cpa16(sb + so,                Ahi + goA);
            cpa16(sb + so + GT_BYTES,     Alo + goA);
            cpa16(sb + so + 2 * GT_BYTES, Bhi + goB);
            cpa16(sb + so + 3 * GT_BYTES, Blo + goB);
        }
        asm volatile("cp.async.commit_group;" ::: "memory");
    };

    const int KT = K >> 5;
    issue(0, 0);

    for (int kt = 0; kt < KT; kt++) {
        if (kt + 1 < KT) {
            issue(kt + 1, (kt + 1) & 1);
            asm volatile("cp.async.wait_group 1;" ::: "memory");
        } else {
            asm volatile("cp.async.wait_group 0;" ::: "memory");
        }
        __syncthreads();

        const uint32_t bufo = (uint32_t)(kt & 1) * GBUF;
        #pragma unroll
        for (int h16 = 0; h16 < 2; h16++) {
            uint32_t ah[4][4], al[4][4];
            #pragma unroll
            for (int mi = 0; mi < 4; mi++) {
                int row = wm * 64 + mi * 16 + grp;
                uint32_t base = sb + bufo + row * 80 + h16 * 32 + tig * 4;
                ah[mi][0] = lds32(base);
                ah[mi][1] = lds32(base + 8 * 80);
                ah[mi][2] = lds32(base + 16);
                ah[mi][3] = lds32(base + 8 * 80 + 16);
                al[mi][0] = lds32(base + GT_BYTES);
                al[mi][1] = lds32(base + GT_BYTES + 8 * 80);
                al[mi][2] = lds32(base + GT_BYTES + 16);
                al[mi][3] = lds32(base + GT_BYTES + 8 * 80 + 16);
            }
            uint32_t bh[4][2], bl[4][2];
            #pragma unroll
            for (int ni = 0; ni < 4; ni++) {
                int row = wn * 32 + ni * 8 + grp;
                uint32_t base = sb + bufo + 2 * GT_BYTES + row * 80 + h16 * 32 + tig * 4;
                bh[ni][0] = lds32(base);
                bh[ni][1] = lds32(base + 16);
                bl[ni][0] = lds32(base + GT_BYTES);
                bl[ni][1] = lds32(base + GT_BYTES + 16);
            }
            #pragma unroll
            for (int mi = 0; mi < 4; mi++)
                #pragma unroll
                for (int ni = 0; ni < 4; ni++) {
                    float* a = acc[mi][ni];
                    mma16816(a[0], a[1], a[2], a[3],
                             ah[mi][0], ah[mi][1], ah[mi][2], ah[mi][3],
                             bh[ni][0], bh[ni][1]);
                    mma16816(a[0], a[1], a[2], a[3],
                             ah[mi][0], ah[mi][1], ah[mi][2], ah[mi][3],
                             bl[ni][0], bl[ni][1]);
                    mma16816(a[0], a[1], a[2], a[3],
                             al[mi][0], al[mi][1], al[mi][2], al[mi][3],
                             bh[ni][0], bh[ni][1]);
                }
        }
        __syncthreads();
    }

    #pragma unroll
    for (int ni = 0; ni < 4; ni++) {
        int gc = n0 + wn * 32 + ni * 8 + tig * 2;
        float bs0 = 0.f, bs1 = 0.f;
        if (bias1) { bs0 += bias1[gc]; bs1 += bias1[gc + 1]; }
        if (bias2) { bs0 += bias2[gc]; bs1 += bias2[gc + 1]; }
        #pragma unroll
        for (int mi = 0; mi < 4; mi++) {
            int gr = m0 + wm * 64 + mi * 16 + grp;
            float* a = acc[mi][ni];
            *(float2*)&C[(size_t)gr * N + gc] = make_float2(a[0] + bs0, a[1] + bs1);
            *(float2*)&C[(size_t)(gr + 8) * N + gc] = make_float2(a[2] + bs0, a[3] + bs1);
        }
    }
}

// ---------------- row softmax over 512 cols ---------------------------------
__global__ __launch_bounds__(256)
void softmax512(const float* __restrict__ logits, float* __restrict__ out)
{
    const int row = blockIdx.x;
    const int tid = threadIdx.x;
    const float* in = logits + (size_t)row * OO;
    float a = in[tid], b = in[tid + 256];

    float m = fmaxf(a, b);
    #pragma unroll
    for (int o = 16; o > 0; o >>= 1)
        m = fmaxf(m, __shfl_xor_sync(0xffffffffu, m, o));
    __shared__ float redm[8];
    __shared__ float reds[8];
    if ((tid & 31) == 0) redm[tid >> 5] = m;
    __syncthreads();
    float mm = redm[0];
    #pragma unroll
    for (int i = 1; i < 8; i++) mm = fmaxf(mm, redm[i]);

    float e0 = expf(a - mm), e1 = expf(b - mm);
    float s = e0 + e1;
    #pragma unroll
    for (int o = 16; o > 0; o >>= 1)
        s += __shfl_xor_sync(0xffffffffu, s, o);
    if ((tid & 31) == 0) reds[tid >> 5] = s;
    __syncthreads();
    float ss = 0.f;
    #pragma unroll
    for (int i = 0; i < 8; i++) ss += reds[i];
    float inv = 1.0f / ss;

    float* op = out + (size_t)row * OO;
    op[tid]       = e0 * inv;
    op[tid + 256] = e1 * inv;
}

// ---------------- launch -----------------------------------------------------
extern "C" void kernel_launch(void* const* d_in, const int* in_sizes, int n_in,
                              void* d_out, int out_size)
{
    const float* x     = (const float*)d_in[0];
    const float* h0    = (const float*)d_in[1];
    const float* W_ih  = (const float*)d_in[2];
    const float* W_hh  = (const float*)d_in[3];
    const float* b_ih  = (const float*)d_in[4];
    const float* b_hh  = (const float*)d_in[5];
    const float* W_out = (const float*)d_in[6];
    const float* b_out = (const float*)d_in[7];
    float* out = (float*)d_out;

    float *pre, *logits, *zfb;
    cudaGetSymbolAddress((void**)&pre,    g_pre);
    cudaGetSymbolAddress((void**)&logits, g_logits);
    cudaGetSymbolAddress((void**)&zfb,    g_zfallback);
    __nv_bfloat16 *xhi, *xlo, *wih_hi, *wih_lo, *wout_hi, *wout_lo, *zhi, *zlo, *h0hi, *h0lo;
    cudaGetSymbolAddress((void**)&xhi, g_xhi);
    cudaGetSymbolAddress((void**)&xlo, g_xlo);
    cudaGetSymbolAddress((void**)&wih_hi, g_wih_hi);
    cudaGetSymbolAddress((void**)&wih_lo, g_wih_lo);
    cudaGetSymbolAddress((void**)&wout_hi, g_wout_hi);
    cudaGetSymbolAddress((void**)&wout_lo, g_wout_lo);
    cudaGetSymbolAddress((void**)&zhi, g_zhi);
    cudaGetSymbolAddress((void**)&zlo, g_zlo);
    cudaGetSymbolAddress((void**)&h0hi, g_h0hi);
    cudaGetSymbolAddress((void**)&h0lo, g_h0lo);

    cudaFuncSetAttribute(bsgemm, cudaFuncAttributeMaxDynamicSharedMemorySize, GSMEM);
    cudaFuncSetAttribute(rnn_persistent, cudaFuncAttributeMaxDynamicSharedMemorySize, RNN_SMEM);

    float* z = (out_size >= (int)((size_t)MM * (OO + HH)))
                 ? out + (size_t)MM * OO : zfb;

    // 0) bf16 hi/lo splits
    split_bf16<<<(MM * II + 255) / 256, 256>>>(x, xhi, xlo, MM * II);
    split_bf16<<<(HH * II + 255) / 256, 256>>>(W_ih, wih_hi, wih_lo, HH * II);
    split_bf16<<<(OO * HH + 255) / 256, 256>>>(W_out, wout_hi, wout_lo, OO * HH);
    split_bf16<<<(BB * HH + 255) / 256, 256>>>(h0, h0hi, h0lo, BB * HH);

    // 1) pre = x @ W_ih^T + b_ih + b_hh
    dim3 g1(MM / 128, HH / 128);
    bsgemm<<<g1, 256, GSMEM>>>(MM, HH, II, xhi, xlo, wih_hi, wih_lo, b_ih, b_hh, pre);

    // 2) recurrence (persistent, 2-group pipeline, flag barrier)
    rnn_persistent<<<RNN_BLOCKS, 256, RNN_SMEM>>>(pre, W_hh, z);

    // 3) logits = z @ W_out^T + b_out
    dim3 g3(MM / 128, OO / 128);
    bsgemm<<<g3, 256, GSMEM>>>(MM, OO, HH, zhi, zlo, wout_hi, wout_lo, b_out, nullptr, logits);

    // 4) softmax rows -> out
    softmax512<<<MM, 256>>>(logits, out);
}